// round 1
// baseline (speedup 1.0000x reference)
#include <cuda_runtime.h>
#include <cuda_bf16.h>
#include <math.h>

#define NN 100000
#define EE 1000000
#define INF 128
#define HH 64
#define BN_EPS 1e-5f

// ---------------- scratch (device globals, no runtime alloc) ----------------
__device__ int   g_indeg[NN];
__device__ int   g_off[NN + 1];
__device__ int   g_cursor[NN];
__device__ int   g_csr[EE];
__device__ float g_dinv[NN];
__device__ int   g_bsum[128];
__device__ int   g_boff[128];
__device__ float g_sum[2][HH];
__device__ float g_sq[2][HH];
__device__ float g_scale[2][HH];
__device__ float g_shift[2][HH];

__device__ float g_h[(size_t)NN * HH];
__device__ float g_bn[(size_t)NN * HH];
__device__ float g_agg[(size_t)NN * HH];

// ---------------- kernels ----------------

__global__ void zero_kernel() {
    int i = blockIdx.x * blockDim.x + threadIdx.x;
    if (i < NN) g_indeg[i] = 0;
    if (i < HH) {
        g_sum[0][i] = 0.f; g_sum[1][i] = 0.f;
        g_sq[0][i]  = 0.f; g_sq[1][i]  = 0.f;
    }
}

__global__ void hist_kernel(const int* __restrict__ dst) {
    int e = blockIdx.x * blockDim.x + threadIdx.x;
    if (e < EE) atomicAdd(&g_indeg[dst[e]], 1);
}

// block-wise sums of indeg (1024 elems / block)
__global__ void degsum_kernel() {
    __shared__ int sh[1024];
    int t = threadIdx.x;
    int idx = blockIdx.x * 1024 + t;
    int v = (idx < NN) ? g_indeg[idx] : 0;
    sh[t] = v;
    __syncthreads();
    for (int s = 512; s > 0; s >>= 1) {
        if (t < s) sh[t] += sh[t + s];
        __syncthreads();
    }
    if (t == 0) g_bsum[blockIdx.x] = sh[0];
}

__global__ void scan_sums_kernel(int nb) {
    if (threadIdx.x == 0 && blockIdx.x == 0) {
        int run = 0;
        for (int b = 0; b < nb; b++) {
            g_boff[b] = run;
            run += g_bsum[b];
        }
        g_off[NN] = run;  // == EE
    }
}

__global__ void scan_final_kernel() {
    __shared__ int sh[1024];
    int t = threadIdx.x;
    int idx = blockIdx.x * 1024 + t;
    int v = (idx < NN) ? g_indeg[idx] : 0;
    sh[t] = v;
    __syncthreads();
    for (int o = 1; o < 1024; o <<= 1) {
        int a = 0;
        if (t >= o) a = sh[t - o];
        __syncthreads();
        sh[t] += a;
        __syncthreads();
    }
    int excl = sh[t] - v;
    if (idx < NN) {
        int off = g_boff[blockIdx.x] + excl;
        g_off[idx] = off;
        g_cursor[idx] = off;
        g_dinv[idx] = rsqrtf((float)(v + 1));  // deg = indeg + self-loop
    }
}

__global__ void fill_kernel(const int* __restrict__ src, const int* __restrict__ dst) {
    int e = blockIdx.x * blockDim.x + threadIdx.x;
    if (e < EE) {
        int d = dst[e];
        int p = atomicAdd(&g_cursor[d], 1);
        g_csr[p] = src[e];
    }
}

// C[M,64] = A[M,K] @ W[K,64]; 64x64 tile per block, 4x4 per thread
template <int K>
__global__ void gemm_kernel(const float* __restrict__ A, const float* __restrict__ W,
                            float* __restrict__ C, int M) {
    const int KC = 32;
    __shared__ float Xs[64][KC + 1];
    __shared__ float Ws[KC][64];
    int t = threadIdx.x;
    int tx = t & 15, ty = t >> 4;
    int m0 = blockIdx.x * 64;
    float acc[4][4] = {};
    for (int kc = 0; kc < K; kc += KC) {
        // X tile: 64 rows x 32 = 512 float4
#pragma unroll
        for (int l = 0; l < 2; l++) {
            int slot = t + l * 256;
            int r = slot >> 3, c4 = slot & 7;
            int row = m0 + r;
            float4 v = make_float4(0.f, 0.f, 0.f, 0.f);
            if (row < M)
                v = reinterpret_cast<const float4*>(A + (size_t)row * K + kc)[c4];
            Xs[r][c4 * 4 + 0] = v.x; Xs[r][c4 * 4 + 1] = v.y;
            Xs[r][c4 * 4 + 2] = v.z; Xs[r][c4 * 4 + 3] = v.w;
        }
        // W tile: 32 rows x 64 = 512 float4
#pragma unroll
        for (int l = 0; l < 2; l++) {
            int slot = t + l * 256;
            int r = slot >> 4, c4 = slot & 15;
            float4 v = reinterpret_cast<const float4*>(W + (size_t)(kc + r) * 64)[c4];
            Ws[r][c4 * 4 + 0] = v.x; Ws[r][c4 * 4 + 1] = v.y;
            Ws[r][c4 * 4 + 2] = v.z; Ws[r][c4 * 4 + 3] = v.w;
        }
        __syncthreads();
#pragma unroll
        for (int k = 0; k < KC; k++) {
            float a[4], b[4];
#pragma unroll
            for (int i = 0; i < 4; i++) a[i] = Xs[ty * 4 + i][k];
#pragma unroll
            for (int j = 0; j < 4; j++) b[j] = Ws[k][tx * 4 + j];
#pragma unroll
            for (int i = 0; i < 4; i++)
#pragma unroll
                for (int j = 0; j < 4; j++)
                    acc[i][j] += a[i] * b[j];
        }
        __syncthreads();
    }
#pragma unroll
    for (int i = 0; i < 4; i++) {
        int row = m0 + ty * 4 + i;
        if (row < M) {
            float4 o = make_float4(acc[i][0], acc[i][1], acc[i][2], acc[i][3]);
            reinterpret_cast<float4*>(C + (size_t)row * 64)[tx] = o;
        }
    }
}

// one warp per node; lane handles channels (2*lane, 2*lane+1)
__global__ void agg_kernel(const float* __restrict__ h, const float* __restrict__ bias,
                           float* __restrict__ out) {
    int warp = (blockIdx.x * blockDim.x + threadIdx.x) >> 5;
    int lane = threadIdx.x & 31;
    if (warp >= NN) return;
    int i = warp;
    float di = g_dinv[i];
    const float2* h2 = reinterpret_cast<const float2*>(h);
    float2 acc = h2[(size_t)i * 32 + lane];
    acc.x *= di; acc.y *= di;  // self-loop: h[i]*dinv[i]  (outer dinv[i] applied at end)
    int e0 = g_off[i], e1 = g_off[i + 1];
    for (int j = e0; j < e1; j++) {
        int s = g_csr[j];
        float ds = g_dinv[s];
        float2 v = h2[(size_t)s * 32 + lane];
        acc.x += v.x * ds;
        acc.y += v.y * ds;
    }
    float2 b = reinterpret_cast<const float2*>(bias)[lane];
    float2 o;
    o.x = acc.x * di + b.x;
    o.y = acc.y * di + b.y;
    reinterpret_cast<float2*>(out)[(size_t)i * 32 + lane] = o;
}

__global__ void stats_kernel(const float* __restrict__ v, int layer) {
    int c = threadIdx.x & 63;
    int rg = threadIdx.x >> 6;  // 0..3
    float s = 0.f, s2 = 0.f;
    for (int r = blockIdx.x * 4 + rg; r < NN; r += gridDim.x * 4) {
        float x = v[(size_t)r * 64 + c];
        s += x;
        s2 += x * x;
    }
    __shared__ float sh[256], sh2[256];
    sh[threadIdx.x] = s;
    sh2[threadIdx.x] = s2;
    __syncthreads();
    if (rg == 0) {
        s  = sh[c] + sh[c + 64] + sh[c + 128] + sh[c + 192];
        s2 = sh2[c] + sh2[c + 64] + sh2[c + 128] + sh2[c + 192];
        atomicAdd(&g_sum[layer][c], s);
        atomicAdd(&g_sq[layer][c], s2);
    }
}

__global__ void bnprep_kernel(int layer, const float* __restrict__ gamma,
                              const float* __restrict__ beta) {
    int c = threadIdx.x;
    if (c < HH) {
        float m   = g_sum[layer][c] * (1.0f / NN);
        float var = g_sq[layer][c] * (1.0f / NN) - m * m;
        float sc  = gamma[c] * rsqrtf(var + BN_EPS);
        g_scale[layer][c] = sc;
        g_shift[layer][c] = beta[c] - m * sc;
    }
}

__global__ void bnapply_kernel(const float* __restrict__ v, int layer,
                               float* __restrict__ out) {
    int idx = blockIdx.x * blockDim.x + threadIdx.x;  // over NN*16 float4
    if (idx >= NN * 16) return;
    float4 x = reinterpret_cast<const float4*>(v)[idx];
    int c = (idx & 15) * 4;
    x.x = fmaxf(fmaf(x.x, g_scale[layer][c + 0], g_shift[layer][c + 0]), 0.f);
    x.y = fmaxf(fmaf(x.y, g_scale[layer][c + 1], g_shift[layer][c + 1]), 0.f);
    x.z = fmaxf(fmaf(x.z, g_scale[layer][c + 2], g_shift[layer][c + 2]), 0.f);
    x.w = fmaxf(fmaf(x.w, g_scale[layer][c + 3], g_shift[layer][c + 3]), 0.f);
    reinterpret_cast<float4*>(out)[idx] = x;
}

// ---------------- launch ----------------
extern "C" void kernel_launch(void* const* d_in, const int* in_sizes, int n_in,
                              void* d_out, int out_size) {
    const float* x   = (const float*)d_in[0];
    const int*   ei  = (const int*)d_in[1];
    const float* W1  = (const float*)d_in[2];
    const float* b1  = (const float*)d_in[3];
    const float* g1  = (const float*)d_in[4];
    const float* bt1 = (const float*)d_in[5];
    const float* W2  = (const float*)d_in[6];
    const float* b2  = (const float*)d_in[7];
    const float* g2  = (const float*)d_in[8];
    const float* bt2 = (const float*)d_in[9];
    float* out = (float*)d_out;

    const int* src = ei;
    const int* dst = ei + EE;

    float *hP = nullptr, *bnP = nullptr, *aggP = nullptr;
    cudaGetSymbolAddress((void**)&hP, g_h);
    cudaGetSymbolAddress((void**)&bnP, g_bn);
    cudaGetSymbolAddress((void**)&aggP, g_agg);

    const int NB = (NN + 1023) / 1024;  // 98

    zero_kernel<<<(NN + 255) / 256, 256>>>();
    hist_kernel<<<(EE + 255) / 256, 256>>>(dst);
    degsum_kernel<<<NB, 1024>>>();
    scan_sums_kernel<<<1, 32>>>(NB);
    scan_final_kernel<<<NB, 1024>>>();
    fill_kernel<<<(EE + 255) / 256, 256>>>(src, dst);

    // ---- layer 1 ----
    gemm_kernel<INF><<<(NN + 63) / 64, 256>>>(x, W1, hP, NN);
    agg_kernel<<<(NN * 32 + 255) / 256, 256>>>(hP, b1, aggP);
    stats_kernel<<<512, 256>>>(aggP, 0);
    bnprep_kernel<<<1, 64>>>(0, g1, bt1);
    bnapply_kernel<<<(NN * 16 + 255) / 256, 256>>>(aggP, 0, bnP);

    // ---- layer 2 ----
    gemm_kernel<HH><<<(NN + 63) / 64, 256>>>(bnP, W2, hP, NN);
    agg_kernel<<<(NN * 32 + 255) / 256, 256>>>(hP, b2, aggP);
    stats_kernel<<<512, 256>>>(aggP, 1);
    bnprep_kernel<<<1, 64>>>(1, g2, bt2);
    bnapply_kernel<<<(NN * 16 + 255) / 256, 256>>>(aggP, 1, out);
}

// round 2
// speedup vs baseline: 1.1436x; 1.1436x over previous
#include <cuda_runtime.h>
#include <cuda_bf16.h>
#include <math.h>

#define NN 100000
#define EE 1000000
#define INF 128
#define HH 64
#define BN_EPS 1e-5f

// ---------------- scratch (device globals, no runtime alloc) ----------------
__device__ int   g_indeg[NN];
__device__ int   g_off[NN + 1];
__device__ int   g_cursor[NN];
__device__ int   g_csr[EE];
__device__ float g_dinv[NN];
__device__ int   g_bsum[128];
__device__ int   g_boff[128];
__device__ float g_sum[2][HH];
__device__ float g_sq[2][HH];
__device__ float g_scale[2][HH];
__device__ float g_shift[2][HH];

__device__ float g_h[(size_t)NN * HH];    // GEMM output, pre-scaled by dinv[row]
__device__ float g_agg[(size_t)NN * HH];  // aggregation output (pre-BN)

// ---------------- graph build ----------------

__global__ void zero_kernel() {
    int i = blockIdx.x * blockDim.x + threadIdx.x;
    if (i < NN) g_indeg[i] = 0;
    if (i < HH) {
        g_sum[0][i] = 0.f; g_sum[1][i] = 0.f;
        g_sq[0][i]  = 0.f; g_sq[1][i]  = 0.f;
    }
}

__global__ void hist_kernel(const int* __restrict__ dst) {
    int e = blockIdx.x * blockDim.x + threadIdx.x;
    if (e < EE) atomicAdd(&g_indeg[dst[e]], 1);
}

__global__ void degsum_kernel() {
    __shared__ int sh[1024];
    int t = threadIdx.x;
    int idx = blockIdx.x * 1024 + t;
    int v = (idx < NN) ? g_indeg[idx] : 0;
    sh[t] = v;
    __syncthreads();
    for (int s = 512; s > 0; s >>= 1) {
        if (t < s) sh[t] += sh[t + s];
        __syncthreads();
    }
    if (t == 0) g_bsum[blockIdx.x] = sh[0];
}

// parallel 128-wide scan of block sums (nb <= 128)
__global__ void scan_sums_kernel(int nb) {
    __shared__ int sh[128];
    int t = threadIdx.x;
    int v = (t < nb) ? g_bsum[t] : 0;
    sh[t] = v;
    __syncthreads();
    for (int o = 1; o < 128; o <<= 1) {
        int a = (t >= o) ? sh[t - o] : 0;
        __syncthreads();
        sh[t] += a;
        __syncthreads();
    }
    if (t < nb) g_boff[t] = sh[t] - v;     // exclusive
    if (t == nb - 1) g_off[NN] = sh[t];    // == EE
}

__global__ void scan_final_kernel() {
    __shared__ int sh[1024];
    int t = threadIdx.x;
    int idx = blockIdx.x * 1024 + t;
    int v = (idx < NN) ? g_indeg[idx] : 0;
    sh[t] = v;
    __syncthreads();
    for (int o = 1; o < 1024; o <<= 1) {
        int a = (t >= o) ? sh[t - o] : 0;
        __syncthreads();
        sh[t] += a;
        __syncthreads();
    }
    int excl = sh[t] - v;
    if (idx < NN) {
        int off = g_boff[blockIdx.x] + excl;
        g_off[idx] = off;
        g_cursor[idx] = off;
        g_dinv[idx] = rsqrtf((float)(v + 1));  // deg = indeg + self-loop
    }
}

__global__ void fill_kernel(const int* __restrict__ src, const int* __restrict__ dst) {
    int e = blockIdx.x * blockDim.x + threadIdx.x;
    if (e < EE) {
        int d = dst[e];
        int p = atomicAdd(&g_cursor[d], 1);
        g_csr[p] = src[e];
    }
}

// ---------------- GEMM: C[row] = dinv[row] * (bn_relu?(A[row]) @ W), 128x64 tile ----------------
template <int K, int DO_BN>
__global__ void gemm_kernel(const float* __restrict__ A, const float* __restrict__ W,
                            float* __restrict__ C, int layer) {
    const int KC = 32;
    __shared__ float Xs[128][KC + 1];
    __shared__ float Ws[KC][64];
    __shared__ float s_scale[64], s_shift[64];
    int t = threadIdx.x;
    if (DO_BN) {
        if (t < 64) { s_scale[t] = g_scale[layer][t]; s_shift[t] = g_shift[layer][t]; }
        __syncthreads();
    }
    int tx = t & 15, ty = t >> 4;
    int m0 = blockIdx.x * 128;
    float acc[8][4] = {};
    for (int kc = 0; kc < K; kc += KC) {
        // X tile: 128 rows x 32 cols = 1024 float4
#pragma unroll
        for (int l = 0; l < 4; l++) {
            int slot = t + l * 256;
            int r = slot >> 3, c4 = slot & 7;
            int row = m0 + r;
            float4 v = make_float4(0.f, 0.f, 0.f, 0.f);
            if (row < NN)
                v = reinterpret_cast<const float4*>(A + (size_t)row * K + kc)[c4];
            if (DO_BN) {
                int c = kc + c4 * 4;
                v.x = fmaxf(fmaf(v.x, s_scale[c + 0], s_shift[c + 0]), 0.f);
                v.y = fmaxf(fmaf(v.y, s_scale[c + 1], s_shift[c + 1]), 0.f);
                v.z = fmaxf(fmaf(v.z, s_scale[c + 2], s_shift[c + 2]), 0.f);
                v.w = fmaxf(fmaf(v.w, s_scale[c + 3], s_shift[c + 3]), 0.f);
            }
            Xs[r][c4 * 4 + 0] = v.x; Xs[r][c4 * 4 + 1] = v.y;
            Xs[r][c4 * 4 + 2] = v.z; Xs[r][c4 * 4 + 3] = v.w;
        }
        // W tile: 32 rows x 64 cols = 512 float4
#pragma unroll
        for (int l = 0; l < 2; l++) {
            int slot = t + l * 256;
            int r = slot >> 4, c4 = slot & 15;
            float4 v = reinterpret_cast<const float4*>(W + (size_t)(kc + r) * 64)[c4];
            Ws[r][c4 * 4 + 0] = v.x; Ws[r][c4 * 4 + 1] = v.y;
            Ws[r][c4 * 4 + 2] = v.z; Ws[r][c4 * 4 + 3] = v.w;
        }
        __syncthreads();
#pragma unroll
        for (int k = 0; k < KC; k++) {
            float4 bv = *reinterpret_cast<float4*>(&Ws[k][tx * 4]);
            float a[8];
#pragma unroll
            for (int i = 0; i < 8; i++) a[i] = Xs[ty * 8 + i][k];
#pragma unroll
            for (int i = 0; i < 8; i++) {
                acc[i][0] = fmaf(a[i], bv.x, acc[i][0]);
                acc[i][1] = fmaf(a[i], bv.y, acc[i][1]);
                acc[i][2] = fmaf(a[i], bv.z, acc[i][2]);
                acc[i][3] = fmaf(a[i], bv.w, acc[i][3]);
            }
        }
        __syncthreads();
    }
#pragma unroll
    for (int i = 0; i < 8; i++) {
        int row = m0 + ty * 8 + i;
        if (row < NN) {
            float di = g_dinv[row];
            float4 o = make_float4(acc[i][0] * di, acc[i][1] * di,
                                   acc[i][2] * di, acc[i][3] * di);
            reinterpret_cast<float4*>(C + (size_t)row * 64)[tx] = o;
        }
    }
}

// ---------------- aggregation + fused BN statistics ----------------
// h already scaled by dinv[src]. out[i] = dinv[i]*(h[i] + sum_nbr h[s]) + bias.
// Grid-stride over nodes (one warp per node); per-warp channel stats accumulated
// in registers, reduced via shared atomics, then 128 global atomics per block.
__global__ void aggstats_kernel(const float* __restrict__ h, const float* __restrict__ bias,
                                float* __restrict__ out, int layer) {
    __shared__ float s_sum[64], s_sq[64];
    int t = threadIdx.x;
    if (t < 64) { s_sum[t] = 0.f; s_sq[t] = 0.f; }
    __syncthreads();
    int lane = t & 31;
    int warpId = blockIdx.x * (blockDim.x >> 5) + (t >> 5);
    int totalWarps = gridDim.x * (blockDim.x >> 5);
    float2 b = reinterpret_cast<const float2*>(bias)[lane];
    const float2* h2 = reinterpret_cast<const float2*>(h);
    float sx = 0.f, sy = 0.f, sxx = 0.f, syy = 0.f;

    for (int i = warpId; i < NN; i += totalWarps) {
        float di = g_dinv[i];
        float2 acc = h2[(size_t)i * 32 + lane];  // self-loop term (pre-scaled)
        int e0 = g_off[i], e1 = g_off[i + 1];
        int j = e0;
        for (; j + 3 < e1; j += 4) {
            int s0 = g_csr[j], s1 = g_csr[j + 1], s2 = g_csr[j + 2], s3 = g_csr[j + 3];
            float2 v0 = h2[(size_t)s0 * 32 + lane];
            float2 v1 = h2[(size_t)s1 * 32 + lane];
            float2 v2 = h2[(size_t)s2 * 32 + lane];
            float2 v3 = h2[(size_t)s3 * 32 + lane];
            acc.x += (v0.x + v1.x) + (v2.x + v3.x);
            acc.y += (v0.y + v1.y) + (v2.y + v3.y);
        }
        for (; j < e1; j++) {
            int s = g_csr[j];
            float2 v = h2[(size_t)s * 32 + lane];
            acc.x += v.x; acc.y += v.y;
        }
        float ox = fmaf(acc.x, di, b.x);
        float oy = fmaf(acc.y, di, b.y);
        reinterpret_cast<float2*>(out)[(size_t)i * 32 + lane] = make_float2(ox, oy);
        sx += ox; sxx += ox * ox;
        sy += oy; syy += oy * oy;
    }
    atomicAdd(&s_sum[lane * 2 + 0], sx);
    atomicAdd(&s_sq [lane * 2 + 0], sxx);
    atomicAdd(&s_sum[lane * 2 + 1], sy);
    atomicAdd(&s_sq [lane * 2 + 1], syy);
    __syncthreads();
    if (t < 64) {
        atomicAdd(&g_sum[layer][t], s_sum[t]);
        atomicAdd(&g_sq[layer][t], s_sq[t]);
    }
}

__global__ void bnprep_kernel(int layer, const float* __restrict__ gamma,
                              const float* __restrict__ beta) {
    int c = threadIdx.x;
    if (c < HH) {
        float m   = g_sum[layer][c] * (1.0f / NN);
        float var = g_sq[layer][c] * (1.0f / NN) - m * m;
        float sc  = gamma[c] * rsqrtf(var + BN_EPS);
        g_scale[layer][c] = sc;
        g_shift[layer][c] = beta[c] - m * sc;
    }
}

__global__ void bnapply_kernel(const float* __restrict__ v, int layer,
                               float* __restrict__ out) {
    int idx = blockIdx.x * blockDim.x + threadIdx.x;  // over NN*16 float4
    if (idx >= NN * 16) return;
    float4 x = reinterpret_cast<const float4*>(v)[idx];
    int c = (idx & 15) * 4;
    x.x = fmaxf(fmaf(x.x, g_scale[layer][c + 0], g_shift[layer][c + 0]), 0.f);
    x.y = fmaxf(fmaf(x.y, g_scale[layer][c + 1], g_shift[layer][c + 1]), 0.f);
    x.z = fmaxf(fmaf(x.z, g_scale[layer][c + 2], g_shift[layer][c + 2]), 0.f);
    x.w = fmaxf(fmaf(x.w, g_scale[layer][c + 3], g_shift[layer][c + 3]), 0.f);
    reinterpret_cast<float4*>(out)[idx] = x;
}

// ---------------- launch ----------------
extern "C" void kernel_launch(void* const* d_in, const int* in_sizes, int n_in,
                              void* d_out, int out_size) {
    const float* x   = (const float*)d_in[0];
    const int*   ei  = (const int*)d_in[1];
    const float* W1  = (const float*)d_in[2];
    const float* b1  = (const float*)d_in[3];
    const float* g1  = (const float*)d_in[4];
    const float* bt1 = (const float*)d_in[5];
    const float* W2  = (const float*)d_in[6];
    const float* b2  = (const float*)d_in[7];
    const float* g2  = (const float*)d_in[8];
    const float* bt2 = (const float*)d_in[9];
    float* out = (float*)d_out;

    const int* src = ei;
    const int* dst = ei + EE;

    float *hP = nullptr, *aggP = nullptr;
    cudaGetSymbolAddress((void**)&hP, g_h);
    cudaGetSymbolAddress((void**)&aggP, g_agg);

    const int NB = (NN + 1023) / 1024;  // 98
    const int AGG_BLOCKS = 1184;        // 148 SMs * 8 blocks (256 thr) resident

    zero_kernel<<<(NN + 255) / 256, 256>>>();
    hist_kernel<<<(EE + 255) / 256, 256>>>(dst);
    degsum_kernel<<<NB, 1024>>>();
    scan_sums_kernel<<<1, 128>>>(NB);
    scan_final_kernel<<<NB, 1024>>>();
    fill_kernel<<<(EE + 255) / 256, 256>>>(src, dst);

    // ---- layer 1 ----
    gemm_kernel<INF, 0><<<(NN + 127) / 128, 256>>>(x, W1, hP, 0);
    aggstats_kernel<<<AGG_BLOCKS, 256>>>(hP, b1, aggP, 0);
    bnprep_kernel<<<1, 64>>>(0, g1, bt1);

    // ---- layer 2 (BN+ReLU of layer 1 fused into A-tile load) ----
    gemm_kernel<HH, 1><<<(NN + 127) / 128, 256>>>(aggP, W2, hP, 0);
    aggstats_kernel<<<AGG_BLOCKS, 256>>>(hP, b2, aggP, 1);
    bnprep_kernel<<<1, 64>>>(1, g2, bt2);
    bnapply_kernel<<<(NN * 16 + 255) / 256, 256>>>(aggP, 1, out);
}